// round 3
// baseline (speedup 1.0000x reference)
#include <cuda_runtime.h>
#include <math.h>

// Input order (metadata):
// 0: positions  [N*3] f32
// 1: cell       [9]   f32
// 2: sigma_tab  [NS*NS] f32
// 3: eps_tab    [NS*NS] f32
// 4: shift_tab  [NS*NS] f32
// 5: species    [N]   i32
// 6: pair_i     [P]   i32
// 7: pair_j     [P]   i32
// 8: shifts     [P*3] i32
// out: energy [N] f32

#define MAX_ATOMS 1048576
#define MAX_TAB   64
#define ILP       8

// packed (x, y, z, species-bits) per atom
__device__ float4 g_posw[MAX_ATOMS];

// fused prep: pack positions+species AND zero the output
__global__ void prep_kernel(const float* __restrict__ pos,
                            const int* __restrict__ species,
                            float* __restrict__ out, int n) {
    int i = blockIdx.x * blockDim.x + threadIdx.x;
    if (i < n) {
        float4 v;
        v.x = pos[3 * i + 0];
        v.y = pos[3 * i + 1];
        v.z = pos[3 * i + 2];
        v.w = __int_as_float(species[i]);
        g_posw[i] = v;
        out[i] = 0.0f;
    }
}

__global__ __launch_bounds__(256)
void lj_pair_kernel(const float* __restrict__ cell,
                    const float* __restrict__ sigma_tab,
                    const float* __restrict__ eps_tab,
                    const float* __restrict__ shift_tab,
                    const int*   __restrict__ pair_i,
                    const int*   __restrict__ pair_j,
                    const int*   __restrict__ shifts,
                    float*       __restrict__ out,
                    int P, int ns, int ns2) {
    // fused per-species-pair params: (sigma^6, 4*eps, shift_e)
    __shared__ float4 s_par[MAX_TAB];
    if (threadIdx.x < ns2) {
        float sg = sigma_tab[threadIdx.x];
        float s3 = sg * sg * sg;
        s_par[threadIdx.x] = make_float4(s3 * s3, 4.0f * eps_tab[threadIdx.x],
                                         shift_tab[threadIdx.x], 0.0f);
    }
    __syncthreads();

    const float c00 = cell[0], c01 = cell[1], c02 = cell[2];
    const float c10 = cell[3], c11 = cell[4], c12 = cell[5];
    const float c20 = cell[6], c21 = cell[7], c22 = cell[8];

    const int base = (blockIdx.x * blockDim.x + threadIdx.x) * ILP;
    if (base >= P) return;

    int ii[ILP], jj[ILP];
    float sfx[ILP], sfy[ILP], sfz[ILP];  // shift displacement = S @ cell

    if (base + ILP <= P) {
        // streaming loads, fully vectorized
        int4 vi0 = *reinterpret_cast<const int4*>(pair_i + base);
        int4 vi1 = *reinterpret_cast<const int4*>(pair_i + base + 4);
        int4 vj0 = *reinterpret_cast<const int4*>(pair_j + base);
        int4 vj1 = *reinterpret_cast<const int4*>(pair_j + base + 4);
        ii[0] = vi0.x; ii[1] = vi0.y; ii[2] = vi0.z; ii[3] = vi0.w;
        ii[4] = vi1.x; ii[5] = vi1.y; ii[6] = vi1.z; ii[7] = vi1.w;
        jj[0] = vj0.x; jj[1] = vj0.y; jj[2] = vj0.z; jj[3] = vj0.w;
        jj[4] = vj1.x; jj[5] = vj1.y; jj[6] = vj1.z; jj[7] = vj1.w;

        const int4* sv = reinterpret_cast<const int4*>(shifts + base * 3);
        int s[24];
        #pragma unroll
        for (int q = 0; q < 6; q++) {
            int4 t = sv[q];
            s[4 * q + 0] = t.x; s[4 * q + 1] = t.y;
            s[4 * q + 2] = t.z; s[4 * q + 3] = t.w;
        }
        #pragma unroll
        for (int k = 0; k < ILP; k++) {
            float fx = (float)s[3 * k + 0];
            float fy = (float)s[3 * k + 1];
            float fz = (float)s[3 * k + 2];
            sfx[k] = fx * c00 + fy * c10 + fz * c20;
            sfy[k] = fx * c01 + fy * c11 + fz * c21;
            sfz[k] = fx * c02 + fy * c12 + fz * c22;
        }
    } else {
        #pragma unroll
        for (int k = 0; k < ILP; k++) {
            int p = base + k;
            if (p < P) {
                ii[k] = pair_i[p]; jj[k] = pair_j[p];
                float fx = (float)shifts[3 * p + 0];
                float fy = (float)shifts[3 * p + 1];
                float fz = (float)shifts[3 * p + 2];
                sfx[k] = fx * c00 + fy * c10 + fz * c20;
                sfy[k] = fx * c01 + fy * c11 + fz * c21;
                sfz[k] = fx * c02 + fy * c12 + fz * c22;
            } else {
                ii[k] = -1; jj[k] = -1;
                sfx[k] = sfy[k] = sfz[k] = 0.0f;
            }
        }
    }

    // two half-batches of 4: caps register pressure while keeping 8 gathers
    // in flight at the boundary
    #pragma unroll
    for (int h = 0; h < 2; h++) {
        float4 pwi[4], pwj[4];
        #pragma unroll
        for (int k = 0; k < 4; k++) {
            int m = h * 4 + k;
            int i = ii[m] < 0 ? 0 : ii[m];
            int j = jj[m] < 0 ? 0 : jj[m];
            pwi[k] = g_posw[i];
            pwj[k] = g_posw[j];
        }
        #pragma unroll
        for (int k = 0; k < 4; k++) {
            int m = h * 4 + k;
            if (ii[m] < 0) continue;
            float dx = pwj[k].x - pwi[k].x + sfx[m];
            float dy = pwj[k].y - pwi[k].y + sfy[m];
            float dz = pwj[k].z - pwi[k].z + sfz[m];

            int si = __float_as_int(pwi[k].w);
            int sj = __float_as_int(pwj[k].w);
            float4 par = s_par[si * ns + sj];

            float r2 = dx * dx + dy * dy + dz * dz;
            float r6 = r2 * r2 * r2;
            float sr6 = __fdividef(par.x, r6);
            float sr12 = sr6 * sr6;
            float e = par.y * (sr12 - sr6) - par.z;

            float half = 0.5f * e;
            atomicAdd(out + ii[m], half);
            atomicAdd(out + jj[m], half);
        }
    }
}

extern "C" void kernel_launch(void* const* d_in, const int* in_sizes, int n_in,
                              void* d_out, int out_size) {
    const float* pos       = (const float*)d_in[0];
    const float* cell      = (const float*)d_in[1];
    const float* sigma_tab = (const float*)d_in[2];
    const float* eps_tab   = (const float*)d_in[3];
    const float* shift_tab = (const float*)d_in[4];
    const int*   species   = (const int*)d_in[5];
    const int*   pair_i    = (const int*)d_in[6];
    const int*   pair_j    = (const int*)d_in[7];
    const int*   shifts    = (const int*)d_in[8];
    float*       out       = (float*)d_out;

    int N = in_sizes[5];
    int P = in_sizes[6];
    int ns2 = in_sizes[2];
    int ns = 1;
    while (ns * ns < ns2) ns++;

    prep_kernel<<<(N + 255) / 256, 256>>>(pos, species, out, N);

    int threads = (P + ILP - 1) / ILP;
    lj_pair_kernel<<<(threads + 255) / 256, 256>>>(
        cell, sigma_tab, eps_tab, shift_tab,
        pair_i, pair_j, shifts, out, P, ns, ns2);
}